// round 5
// baseline (speedup 1.0000x reference)
#include <cuda_runtime.h>
#include <cuda_bf16.h>
#include <cstdint>

#define DINL __device__ __forceinline__

// ---------------- smem layout (bytes) ----------------
// biases: 800 floats. W2 tile: 32 rows x RS576. W3 tile: 128 x RS192.
// RA region: GEMM1 x(128x RS320) + W1(128 x RS320) | GEMM4 W4 chunk (128 x RS576)
constexpr int SM_BIAS = 0;
constexpr int SM_W2   = 3200;
constexpr int SM_W3   = 21632;            // 3200 + 32*576
constexpr int SM_A    = 46208;            // 21632 + 128*192
constexpr int SM_W1   = 87168;            // 46208 + 128*320
constexpr int SM_TOTAL= 128128;           // 87168 + 128*320

DINL void mma16816(float c[4], uint32_t a0, uint32_t a1, uint32_t a2, uint32_t a3,
                   uint32_t b0, uint32_t b1) {
    asm volatile("mma.sync.aligned.m16n8k16.row.col.f32.bf16.bf16.f32 "
        "{%0,%1,%2,%3}, {%4,%5,%6,%7}, {%8,%9}, {%0,%1,%2,%3};"
        : "+f"(c[0]), "+f"(c[1]), "+f"(c[2]), "+f"(c[3])
        : "r"(a0), "r"(a1), "r"(a2), "r"(a3), "r"(b0), "r"(b1));
}

// split fp32 pair -> packed bf16 hi (lo16 = even elem) and packed bf16 lo-residual
DINL void split2(float a, float b, uint32_t& h, uint32_t& l) {
    __nv_bfloat16 ha = __float2bfloat16(a), hb = __float2bfloat16(b);
    __nv_bfloat16 la = __float2bfloat16(a - __bfloat162float(ha));
    __nv_bfloat16 lb = __float2bfloat16(b - __bfloat162float(hb));
    h = ((uint32_t)__bfloat16_as_ushort(hb) << 16) | (uint32_t)__bfloat16_as_ushort(ha);
    l = ((uint32_t)__bfloat16_as_ushort(lb) << 16) | (uint32_t)__bfloat16_as_ushort(la);
}

// Fill an [R x KC] fp32 tile (row-major, leading dim ldsrc) into hi/lo interleaved
// fragment layout: row base + (k/16)*64 + ((k&7)>>1)*16 + {hi:0,lo:8} + ((k>>3)&1)*4 + (k&1)*2
DINL void fill_tile(const float* __restrict__ src, int ldsrc,
                    char* __restrict__ dst, int R, int KC, int RS, int t) {
    const int kc4 = KC >> 2;
    const int n4 = R * kc4;
    for (int i = t; i < n4; i += 256) {
        int r = i / kc4;
        int k = (i - r * kc4) << 2;
        float4 v = __ldg((const float4*)(src + (size_t)r * ldsrc + k));
        uint32_t h0, l0, h1, l1;
        split2(v.x, v.y, h0, l0);
        split2(v.z, v.w, h1, l1);
        int q   = (k & 7) >> 1;              // 0 or 2 (k % 4 == 0)
        int sub = ((k >> 3) & 1) << 2;       // byte 0 or 4 within the 8B half
        char* p = dst + (size_t)r * RS + (k >> 4) * 64 + q * 16 + sub;
        *(uint32_t*)(p)      = h0;
        *(uint32_t*)(p + 8)  = l0;
        *(uint32_t*)(p + 16) = h1;           // next q slot
        *(uint32_t*)(p + 24) = l1;
    }
}

// one 16-k step, A from smem (hi/lo), B tile from smem, NJ n-tiles, 3-pass split mma
template<int NJ>
DINL void gemm_step_s(const char* smc, int aoff, int RSa, int boff, int RSb,
                      int g, int q, float (*acc)[4]) {
    uint4 va0 = *(const uint4*)(smc + aoff + (size_t)g * RSa + q * 16);
    uint4 va1 = *(const uint4*)(smc + aoff + (size_t)(g + 8) * RSa + q * 16);
    #pragma unroll
    for (int j = 0; j < NJ; j++) {
        uint4 vb = *(const uint4*)(smc + boff + (size_t)(j * 8 + g) * RSb + q * 16);
        mma16816(acc[j], va0.x, va1.x, va0.y, va1.y, vb.x, vb.y);  // hi*hi
        mma16816(acc[j], va0.x, va1.x, va0.y, va1.y, vb.z, vb.w);  // hi*lo
        mma16816(acc[j], va0.z, va1.z, va0.w, va1.w, vb.x, vb.y);  // lo*hi
    }
}

// one 16-k step, A from registers (chained activations), B from smem
template<int NJ>
DINL void gemm_step_r(const char* smc, const uint32_t ah[4], const uint32_t al[4],
                      int boff, int RSb, int g, int q, float (*acc)[4]) {
    #pragma unroll
    for (int j = 0; j < NJ; j++) {
        uint4 vb = *(const uint4*)(smc + boff + (size_t)(j * 8 + g) * RSb + q * 16);
        mma16816(acc[j], ah[0], ah[1], ah[2], ah[3], vb.x, vb.y);
        mma16816(acc[j], ah[0], ah[1], ah[2], ah[3], vb.z, vb.w);
        mma16816(acc[j], al[0], al[1], al[2], al[3], vb.x, vb.y);
    }
}

__global__ void __launch_bounds__(256, 1) channel_net_kernel(
    const float* __restrict__ x, const float* __restrict__ noise, const float* __restrict__ hch,
    const float* __restrict__ W1, const float* __restrict__ b1,
    const float* __restrict__ W2, const float* __restrict__ b2,
    const float* __restrict__ W3, const float* __restrict__ b3,
    const float* __restrict__ W4, const float* __restrict__ b4,
    float* __restrict__ out)
{
    extern __shared__ char smc[];
    const int t = threadIdx.x;
    const int w = t >> 5, lane = t & 31, g = lane >> 2, q = lane & 3;
    const int row0 = blockIdx.x * 128;
    float* bias = (float*)(smc + SM_BIAS);

    // one-time smem fills (covered by the first chunk's barrier)
    for (int i = t; i < 128; i += 256) bias[i]       = __ldg(b1 + i);
    for (int i = t; i < 32;  i += 256) bias[128 + i] = __ldg(b2 + i);
    for (int i = t; i < 128; i += 256) bias[160 + i] = __ldg(b3 + i);
    for (int i = t; i < 512; i += 256) bias[288 + i] = __ldg(b4 + i);
    fill_tile(W2, 128, smc + SM_W2, 32, 128, 576, t);
    fill_tile(W3, 32,  smc + SM_W3, 128, 32, 192, t);

    float acc[16][4];
    #pragma unroll
    for (int j = 0; j < 16; j++) { acc[j][0]=0.f; acc[j][1]=0.f; acc[j][2]=0.f; acc[j][3]=0.f; }

    const int arow = SM_A + (w * 16) * 320;   // warp's x-row base in the x tile

    // ============== GEMM1: z1[128x128] = x[128x512] @ W1^T, 8 k-chunks of 64 ==============
    for (int c = 0; c < 8; c++) {
        __syncthreads();                                  // buffer free (and start-up fills done)
        fill_tile(x + (size_t)row0 * 512 + c * 64, 512, smc + SM_A,  128, 64, 320, t);
        fill_tile(W1 + c * 64,                     512, smc + SM_W1, 128, 64, 320, t);
        __syncthreads();
        #pragma unroll
        for (int kb = 0; kb < 4; kb++)
            gemm_step_s<16>(smc, arow + kb * 64, 320, SM_W1 + kb * 64, 320, g, q, acc);
    }
    __syncthreads();   // all warps finished reading GEMM1 tiles

    // ---- epilogue 1: +b1, relu, split -> chained A fragments (8 k-blocks) ----
    uint32_t ah[8][4], al[8][4];
    #pragma unroll
    for (int j = 0; j < 16; j++) {
        float bb0 = bias[j * 8 + q * 2], bb1 = bias[j * 8 + q * 2 + 1];
        float v0 = fmaxf(acc[j][0] + bb0, 0.f), v1 = fmaxf(acc[j][1] + bb1, 0.f);
        float v2 = fmaxf(acc[j][2] + bb0, 0.f), v3 = fmaxf(acc[j][3] + bb1, 0.f);
        uint32_t h01, l01, h23, l23;
        split2(v0, v1, h01, l01);
        split2(v2, v3, h23, l23);
        int kb = j >> 1, s = (j & 1) * 2;
        ah[kb][s] = h01; ah[kb][s + 1] = h23;
        al[kb][s] = l01; al[kb][s + 1] = l23;
    }

    // ============== GEMM2: z2[128x32] = z1 @ W2^T (K=128) ==============
    float acc2[4][4];
    #pragma unroll
    for (int j = 0; j < 4; j++) { acc2[j][0]=0.f; acc2[j][1]=0.f; acc2[j][2]=0.f; acc2[j][3]=0.f; }
    #pragma unroll
    for (int kb = 0; kb < 8; kb++)
        gemm_step_r<4>(smc, ah[kb], al[kb], SM_W2 + kb * 64, 576, g, q, acc2);

    // ---- epilogue 2: +b2, power-normalize, rotate by h, +noise ----
    uint32_t a3h[2][4], a3l[2][4];
    {
        float vv[4][4];
        float ssg = 0.f, ssh = 0.f;
        #pragma unroll
        for (int j = 0; j < 4; j++) {
            float bb0 = bias[128 + j * 8 + q * 2], bb1 = bias[128 + j * 8 + q * 2 + 1];
            vv[j][0] = acc2[j][0] + bb0; vv[j][1] = acc2[j][1] + bb1;
            vv[j][2] = acc2[j][2] + bb0; vv[j][3] = acc2[j][3] + bb1;
            ssg += vv[j][0] * vv[j][0] + vv[j][1] * vv[j][1];
            ssh += vv[j][2] * vv[j][2] + vv[j][3] * vv[j][3];
        }
        ssg += __shfl_xor_sync(0xffffffffu, ssg, 1);
        ssg += __shfl_xor_sync(0xffffffffu, ssg, 2);
        ssh += __shfl_xor_sync(0xffffffffu, ssh, 1);
        ssh += __shfl_xor_sync(0xffffffffu, ssh, 2);
        float scg = 4.0f / sqrtf(ssg);       // sqrt(N*0.5) = 4
        float sch = 4.0f / sqrtf(ssh);
        float hc = __ldg(hch), hs = __ldg(hch + 1);
        int rg = row0 + w * 16 + g;
        #pragma unroll
        for (int j = 0; j < 4; j++) {
            float2 ng = __ldg((const float2*)(noise + (size_t)rg * 32 + j * 8 + q * 2));
            float2 nh = __ldg((const float2*)(noise + (size_t)(rg + 8) * 32 + j * 8 + q * 2));
            float y0 = scg * (vv[j][0] * hc - vv[j][1] * hs) + ng.x;
            float y1 = scg * (vv[j][0] * hs + vv[j][1] * hc) + ng.y;
            float y2 = sch * (vv[j][2] * hc - vv[j][3] * hs) + nh.x;
            float y3 = sch * (vv[j][2] * hs + vv[j][3] * hc) + nh.y;
            uint32_t h01, l01, h23, l23;
            split2(y0, y1, h01, l01);
            split2(y2, y3, h23, l23);
            int kb = j >> 1, s = (j & 1) * 2;
            a3h[kb][s] = h01; a3h[kb][s + 1] = h23;
            a3l[kb][s] = l01; a3l[kb][s + 1] = l23;
        }
    }

    // ============== GEMM3: d[128x128] = y @ W3^T (K=32) ==============
    #pragma unroll
    for (int j = 0; j < 16; j++) { acc[j][0]=0.f; acc[j][1]=0.f; acc[j][2]=0.f; acc[j][3]=0.f; }
    #pragma unroll
    for (int kb = 0; kb < 2; kb++)
        gemm_step_r<16>(smc, a3h[kb], a3l[kb], SM_W3 + kb * 64, 192, g, q, acc);

    // ---- epilogue 3: +b3, relu, split -> A4 fragments ----
    #pragma unroll
    for (int j = 0; j < 16; j++) {
        float bb0 = bias[160 + j * 8 + q * 2], bb1 = bias[160 + j * 8 + q * 2 + 1];
        float v0 = fmaxf(acc[j][0] + bb0, 0.f), v1 = fmaxf(acc[j][1] + bb1, 0.f);
        float v2 = fmaxf(acc[j][2] + bb0, 0.f), v3 = fmaxf(acc[j][3] + bb1, 0.f);
        uint32_t h01, l01, h23, l23;
        split2(v0, v1, h01, l01);
        split2(v2, v3, h23, l23);
        int kb = j >> 1, s = (j & 1) * 2;
        ah[kb][s] = h01; ah[kb][s + 1] = h23;
        al[kb][s] = l01; al[kb][s + 1] = l23;
    }

    // ============== GEMM4: out[128x512] = d @ W4^T, 4 n-chunks of 128 ==============
    for (int nc = 0; nc < 4; nc++) {
        __syncthreads();                      // previous chunk / GEMM3 smem reads done
        fill_tile(W4 + (size_t)nc * 128 * 128, 128, smc + SM_A, 128, 128, 576, t);
        __syncthreads();
        #pragma unroll
        for (int j = 0; j < 16; j++) { acc[j][0]=0.f; acc[j][1]=0.f; acc[j][2]=0.f; acc[j][3]=0.f; }
        #pragma unroll
        for (int kb = 0; kb < 8; kb++)
            gemm_step_r<16>(smc, ah[kb], al[kb], SM_A + kb * 64, 576, g, q, acc);
        // epilogue 4: +b4, store fp32
        #pragma unroll
        for (int j = 0; j < 16; j++) {
            int col = nc * 128 + j * 8 + q * 2;
            float bb0 = bias[288 + col], bb1 = bias[288 + col + 1];
            float2 o0 = make_float2(acc[j][0] + bb0, acc[j][1] + bb1);
            float2 o1 = make_float2(acc[j][2] + bb0, acc[j][3] + bb1);
            *(float2*)(out + (size_t)(row0 + w * 16 + g)     * 512 + col) = o0;
            *(float2*)(out + (size_t)(row0 + w * 16 + g + 8) * 512 + col) = o1;
        }
    }
}

extern "C" void kernel_launch(void* const* d_in, const int* in_sizes, int n_in,
                              void* d_out, int out_size) {
    const float* x     = (const float*)d_in[0];
    const float* noise = (const float*)d_in[1];
    const float* hch   = (const float*)d_in[2];
    const float* W1    = (const float*)d_in[3];
    const float* b1    = (const float*)d_in[4];
    const float* W2    = (const float*)d_in[5];
    const float* b2    = (const float*)d_in[6];
    const float* W3    = (const float*)d_in[7];
    const float* b3    = (const float*)d_in[8];
    const float* W4    = (const float*)d_in[9];
    const float* b4    = (const float*)d_in[10];
    float* out = (float*)d_out;

    static int configured = 0;
    if (!configured) {
        cudaFuncSetAttribute(channel_net_kernel,
                             cudaFuncAttributeMaxDynamicSharedMemorySize, SM_TOTAL);
        configured = 1;
    }
    channel_net_kernel<<<1024, 256, SM_TOTAL>>>(
        x, noise, hch, W1, b1, W2, b2, W3, b3, W4, b4, out);
}

// round 6
// speedup vs baseline: 1.6704x; 1.6704x over previous
#include <cuda_runtime.h>
#include <cuda_bf16.h>
#include <cstdint>

#define DINL __device__ __forceinline__

// ---------------- smem layout (bytes) ----------------
constexpr int SM_BIAS = 0;            // 800 floats (b1|b2|b3|b4)
constexpr int SM_W2   = 3200;         // 32 rows x RS576
constexpr int SM_W3   = 21632;        // 128 rows x RS192
constexpr int SM_A    = 46208;        // 2 x 40960 double buffer (W1 chunks / W4 chunks)
constexpr int SM_BUFS = 40960;
constexpr int SM_TOTAL= SM_A + 2 * SM_BUFS;   // 128128

// ---------------- preconverted weight fragments (global scratch) ----------------
// W1: chunk-major [8 chunks][128 rows][256B]  (chunk = 64 k, 4 kb of 64B)
// W4: row-major   [512 rows][512B]            (8 kb of 64B)
// W2: [32 rows][512B]   W3: [128 rows][128B]
__device__ __align__(256) unsigned char gW1[8 * 128 * 256];
__device__ __align__(256) unsigned char gW2[32 * 512];
__device__ __align__(256) unsigned char gW3[128 * 128];
__device__ __align__(256) unsigned char gW4[512 * 512];

DINL void mma16816(float c[4], uint32_t a0, uint32_t a1, uint32_t a2, uint32_t a3,
                   uint32_t b0, uint32_t b1) {
    asm volatile("mma.sync.aligned.m16n8k16.row.col.f32.bf16.bf16.f32 "
        "{%0,%1,%2,%3}, {%4,%5,%6,%7}, {%8,%9}, {%0,%1,%2,%3};"
        : "+f"(c[0]), "+f"(c[1]), "+f"(c[2]), "+f"(c[3])
        : "r"(a0), "r"(a1), "r"(a2), "r"(a3), "r"(b0), "r"(b1));
}

// split fp32 pair -> packed bf16 hi (lo16 = even elem) and packed bf16 lo-residual
DINL void split2(float a, float b, uint32_t& h, uint32_t& l) {
    __nv_bfloat16 ha = __float2bfloat16(a), hb = __float2bfloat16(b);
    __nv_bfloat16 la = __float2bfloat16(a - __bfloat162float(ha));
    __nv_bfloat16 lb = __float2bfloat16(b - __bfloat162float(hb));
    h = ((uint32_t)__bfloat16_as_ushort(hb) << 16) | (uint32_t)__bfloat16_as_ushort(ha);
    l = ((uint32_t)__bfloat16_as_ushort(lb) << 16) | (uint32_t)__bfloat16_as_ushort(la);
}

// write one 4-k group of a fragment row: 16B slot layout {h0, h1@+16, l0@+8, l1@+24}
DINL void frag_store(unsigned char* p, float4 v) {
    uint32_t h0, l0, h1, l1;
    split2(v.x, v.y, h0, l0);
    split2(v.z, v.w, h1, l1);
    *(uint32_t*)(p)      = h0;
    *(uint32_t*)(p + 8)  = l0;
    *(uint32_t*)(p + 16) = h1;
    *(uint32_t*)(p + 24) = l1;
}

// ---------------- setup kernel: convert weights to fragment layout ----------------
__global__ void __launch_bounds__(256) setup_kernel(
    const float* __restrict__ W1, const float* __restrict__ W2,
    const float* __restrict__ W3, const float* __restrict__ W4)
{
    int i = blockIdx.x * 256 + threadIdx.x;
    if (i < 16384) {                       // W1 [128 x 512], chunk-major dst
        int r = i >> 7, k = (i & 127) << 2;
        float4 v = __ldg((const float4*)(W1 + (size_t)r * 512 + k));
        int c = k >> 6, kb = (k >> 4) & 3, q = (k & 7) >> 1, sub = ((k >> 3) & 1) << 2;
        frag_store(gW1 + c * 32768 + r * 256 + kb * 64 + q * 16 + sub, v);
    } else if (i < 32768) {                // W4 [512 x 128]
        int j = i - 16384;
        int r = j >> 5, k = (j & 31) << 2;
        float4 v = __ldg((const float4*)(W4 + (size_t)r * 128 + k));
        int kb = k >> 4, q = (k & 7) >> 1, sub = ((k >> 3) & 1) << 2;
        frag_store(gW4 + r * 512 + kb * 64 + q * 16 + sub, v);
    } else if (i < 33792) {                // W2 [32 x 128]
        int j = i - 32768;
        int r = j >> 5, k = (j & 31) << 2;
        float4 v = __ldg((const float4*)(W2 + (size_t)r * 128 + k));
        int kb = k >> 4, q = (k & 7) >> 1, sub = ((k >> 3) & 1) << 2;
        frag_store(gW2 + r * 512 + kb * 64 + q * 16 + sub, v);
    } else if (i < 34816) {                // W3 [128 x 32]
        int j = i - 33792;
        int r = j >> 3, k = (j & 7) << 2;
        float4 v = __ldg((const float4*)(W3 + (size_t)r * 32 + k));
        int kb = k >> 4, q = (k & 7) >> 1, sub = ((k >> 3) & 1) << 2;
        frag_store(gW3 + r * 128 + kb * 64 + q * 16 + sub, v);
    }
}

// ---------------- cp.async helpers ----------------
DINL void cpa16(uint32_t sdst, const void* gsrc) {
    asm volatile("cp.async.cg.shared.global [%0], [%1], 16;"
                 :: "r"(sdst), "l"(gsrc) : "memory");
}
#define CPCOMMIT() asm volatile("cp.async.commit_group;" ::: "memory")
#define CPWAIT1()  asm volatile("cp.async.wait_group 1;" ::: "memory")
#define CPWAIT0()  asm volatile("cp.async.wait_group 0;" ::: "memory")

DINL uint32_t smem_u32(const void* p) {
    uint32_t a;
    asm("{ .reg .u64 t; cvta.to.shared.u64 t, %1; cvt.u32.u64 %0, t; }" : "=r"(a) : "l"(p));
    return a;
}

// copy ROWS x (IPR*16B) from contiguous gmem into smem with row stride RSD (pad)
template<int ROWS, int IPR, int RSD>
DINL void cppad(uint32_t sdst, const unsigned char* __restrict__ gsrc, int t) {
    constexpr int TOT = ROWS * IPR;
    #pragma unroll
    for (int i = t; i < TOT; i += 256) {
        int r = i / IPR, ii = i - r * IPR;
        cpa16(sdst + r * RSD + ii * 16, gsrc + (size_t)i * 16);
    }
}

// one 16-k step, A from registers, B from smem, NJ n-tiles, 3-pass split mma
template<int NJ>
DINL void gemm_step_r(const char* smc, const uint32_t ah[4], const uint32_t al[4],
                      int boff, int RSb, int g, int q, float (*acc)[4]) {
    #pragma unroll
    for (int j = 0; j < NJ; j++) {
        uint4 vb = *(const uint4*)(smc + boff + (size_t)(j * 8 + g) * RSb + q * 16);
        mma16816(acc[j], ah[0], ah[1], ah[2], ah[3], vb.x, vb.y);
        mma16816(acc[j], ah[0], ah[1], ah[2], ah[3], vb.z, vb.w);
        mma16816(acc[j], al[0], al[1], al[2], al[3], vb.x, vb.y);
    }
}

// prefetch x fragments for one 64-k chunk into fp32 regs
DINL void loadx(const float* __restrict__ xrow, int c, float2 xf[16], int q) {
    const float* p0 = xrow;              // row g
    const float* p1 = xrow + 8 * 512;    // row g+8
    #pragma unroll
    for (int kb = 0; kb < 4; kb++) {
        int k0 = c * 64 + kb * 16 + q * 2;
        xf[kb * 4 + 0] = __ldg((const float2*)(p0 + k0));
        xf[kb * 4 + 1] = __ldg((const float2*)(p1 + k0));
        xf[kb * 4 + 2] = __ldg((const float2*)(p0 + k0 + 8));
        xf[kb * 4 + 3] = __ldg((const float2*)(p1 + k0 + 8));
    }
}

// GEMM1 chunk compute: 4 kb x 16 j, A converted inline from xf
DINL void compute_chunk1(const char* smc, int buf, const float2 xf[16],
                         int g, int q, float (*acc)[4]) {
    #pragma unroll
    for (int kb = 0; kb < 4; kb++) {
        uint32_t ah[4], al[4];
        #pragma unroll
        for (int s = 0; s < 4; s++)
            split2(xf[kb * 4 + s].x, xf[kb * 4 + s].y, ah[s], al[s]);
        gemm_step_r<16>(smc, ah, al, buf + kb * 64, 320, g, q, acc);
    }
}

__global__ void __launch_bounds__(256, 1) channel_net_kernel(
    const float* __restrict__ x, const float* __restrict__ noise, const float* __restrict__ hch,
    const float* __restrict__ b1, const float* __restrict__ b2,
    const float* __restrict__ b3, const float* __restrict__ b4,
    float* __restrict__ out)
{
    extern __shared__ char smc[];
    const uint32_t sb = smem_u32(smc);
    const int t = threadIdx.x;
    const int w = t >> 5, lane = t & 31, g = lane >> 2, q = lane & 3;
    const int row0 = blockIdx.x * 128;
    float* bias = (float*)(smc + SM_BIAS);

    // bias fills (plain loads; consumed only after GEMM1's barriers)
    for (int i = t; i < 128; i += 256) bias[i]       = __ldg(b1 + i);
    for (int i = t; i < 32;  i += 256) bias[128 + i] = __ldg(b2 + i);
    for (int i = t; i < 128; i += 256) bias[160 + i] = __ldg(b3 + i);
    for (int i = t; i < 512; i += 256) bias[288 + i] = __ldg(b4 + i);

    // prologue: W2 + W3 + W1 chunk0 -> group0 ; W1 chunk1 -> group1
    cppad<32, 32, 576>(sb + SM_W2, gW2, t);
    cppad<128, 8, 192>(sb + SM_W3, gW3, t);
    cppad<128, 16, 320>(sb + SM_A, gW1, t);
    CPCOMMIT();
    cppad<128, 16, 320>(sb + SM_A + SM_BUFS, gW1 + 32768, t);
    CPCOMMIT();

    const float* xrow = x + (size_t)(row0 + w * 16 + g) * 512;
    float2 xfA[16], xfB[16];
    loadx(xrow, 0, xfA, q);

    float acc[16][4];
    #pragma unroll
    for (int j = 0; j < 16; j++) { acc[j][0]=0.f; acc[j][1]=0.f; acc[j][2]=0.f; acc[j][3]=0.f; }

    // ============== GEMM1: z1[128x128] = x @ W1^T, 8 chunks of 64 k ==============
    for (int c = 0; c < 8; c += 2) {
        loadx(xrow, c + 1, xfB, q);
        CPWAIT1(); __syncthreads();
        compute_chunk1(smc, SM_A, xfA, g, q, acc);
        __syncthreads();
        if (c + 2 < 8) { cppad<128, 16, 320>(sb + SM_A, gW1 + (size_t)(c + 2) * 32768, t); CPCOMMIT(); }
        if (c + 2 < 8) loadx(xrow, c + 2, xfA, q);
        if (c == 6) { CPWAIT0(); } else { CPWAIT1(); }
        __syncthreads();
        compute_chunk1(smc, SM_A + SM_BUFS, xfB, g, q, acc);
        __syncthreads();
        if (c + 3 < 8) { cppad<128, 16, 320>(sb + SM_A + SM_BUFS, gW1 + (size_t)(c + 3) * 32768, t); CPCOMMIT(); }
    }

    // kick off W4 chunk 0/1 copies — overlap with GEMM2/3 and epilogues
    cppad<64, 32, 576>(sb + SM_A, gW4, t);
    CPCOMMIT();
    cppad<64, 32, 576>(sb + SM_A + SM_BUFS, gW4 + 64 * 512, t);
    CPCOMMIT();

    // ---- epilogue 1: +b1, relu, split -> chained A fragments ----
    uint32_t ah[8][4], al[8][4];
    #pragma unroll
    for (int j = 0; j < 16; j++) {
        float bb0 = bias[j * 8 + q * 2], bb1 = bias[j * 8 + q * 2 + 1];
        float v0 = fmaxf(acc[j][0] + bb0, 0.f), v1 = fmaxf(acc[j][1] + bb1, 0.f);
        float v2 = fmaxf(acc[j][2] + bb0, 0.f), v3 = fmaxf(acc[j][3] + bb1, 0.f);
        uint32_t h01, l01, h23, l23;
        split2(v0, v1, h01, l01);
        split2(v2, v3, h23, l23);
        int kb = j >> 1, s = (j & 1) * 2;
        ah[kb][s] = h01; ah[kb][s + 1] = h23;
        al[kb][s] = l01; al[kb][s + 1] = l23;
    }

    // ============== GEMM2: z2[128x32] = z1 @ W2^T (K=128) ==============
    float acc2[4][4];
    #pragma unroll
    for (int j = 0; j < 4; j++) { acc2[j][0]=0.f; acc2[j][1]=0.f; acc2[j][2]=0.f; acc2[j][3]=0.f; }
    #pragma unroll
    for (int kb = 0; kb < 8; kb++)
        gemm_step_r<4>(smc, ah[kb], al[kb], SM_W2 + kb * 64, 576, g, q, acc2);

    // ---- epilogue 2: +b2, power-normalize, rotate by h, +noise ----
    uint32_t a3h[2][4], a3l[2][4];
    {
        float vv[4][4];
        float ssg = 0.f, ssh = 0.f;
        #pragma unroll
        for (int j = 0; j < 4; j++) {
            float bb0 = bias[128 + j * 8 + q * 2], bb1 = bias[128 + j * 8 + q * 2 + 1];
            vv[j][0] = acc2[j][0] + bb0; vv[j][1] = acc2[j][1] + bb1;
            vv[j][2] = acc2[j][2] + bb0; vv[j][3] = acc2[j][3] + bb1;
            ssg += vv[j][0] * vv[j][0] + vv[j][1] * vv[j][1];
            ssh += vv[j][2] * vv[j][2] + vv[j][3] * vv[j][3];
        }
        ssg += __shfl_xor_sync(0xffffffffu, ssg, 1);
        ssg += __shfl_xor_sync(0xffffffffu, ssg, 2);
        ssh += __shfl_xor_sync(0xffffffffu, ssh, 1);
        ssh += __shfl_xor_sync(0xffffffffu, ssh, 2);
        float scg = 4.0f / sqrtf(ssg);       // sqrt(N*0.5) = 4
        float sch = 4.0f / sqrtf(ssh);
        float hc = __ldg(hch), hs = __ldg(hch + 1);
        int rg = row0 + w * 16 + g;
        #pragma unroll
        for (int j = 0; j < 4; j++) {
            float2 ng = __ldg((const float2*)(noise + (size_t)rg * 32 + j * 8 + q * 2));
            float2 nh = __ldg((const float2*)(noise + (size_t)(rg + 8) * 32 + j * 8 + q * 2));
            float y0 = scg * (vv[j][0] * hc - vv[j][1] * hs) + ng.x;
            float y1 = scg * (vv[j][0] * hs + vv[j][1] * hc) + ng.y;
            float y2 = sch * (vv[j][2] * hc - vv[j][3] * hs) + nh.x;
            float y3 = sch * (vv[j][2] * hs + vv[j][3] * hc) + nh.y;
            uint32_t h01, l01, h23, l23;
            split2(y0, y1, h01, l01);
            split2(y2, y3, h23, l23);
            int kb = j >> 1, s = (j & 1) * 2;
            a3h[kb][s] = h01; a3h[kb][s + 1] = h23;
            a3l[kb][s] = l01; a3l[kb][s + 1] = l23;
        }
    }

    // ============== GEMM3: d[128x128] = y @ W3^T (K=32) ==============
    #pragma unroll
    for (int j = 0; j < 16; j++) { acc[j][0]=0.f; acc[j][1]=0.f; acc[j][2]=0.f; acc[j][3]=0.f; }
    #pragma unroll
    for (int kb = 0; kb < 2; kb++)
        gemm_step_r<16>(smc, a3h[kb], a3l[kb], SM_W3 + kb * 64, 192, g, q, acc);

    // ---- epilogue 3: +b3, relu, split -> A4 fragments ----
    #pragma unroll
    for (int j = 0; j < 16; j++) {
        float bb0 = bias[160 + j * 8 + q * 2], bb1 = bias[160 + j * 8 + q * 2 + 1];
        float v0 = fmaxf(acc[j][0] + bb0, 0.f), v1 = fmaxf(acc[j][1] + bb1, 0.f);
        float v2 = fmaxf(acc[j][2] + bb0, 0.f), v3 = fmaxf(acc[j][3] + bb1, 0.f);
        uint32_t h01, l01, h23, l23;
        split2(v0, v1, h01, l01);
        split2(v2, v3, h23, l23);
        int kb = j >> 1, s = (j & 1) * 2;
        ah[kb][s] = h01; ah[kb][s + 1] = h23;
        al[kb][s] = l01; al[kb][s + 1] = l23;
    }

    // ============== GEMM4: out[128x512] = d @ W4^T, 8 n-chunks of 64 ==============
    for (int nc = 0; nc < 8; nc++) {
        if (nc == 7) { CPWAIT0(); } else { CPWAIT1(); }
        __syncthreads();
        int buf = SM_A + (nc & 1) * SM_BUFS;
        float acc4[8][4];
        #pragma unroll
        for (int j = 0; j < 8; j++) { acc4[j][0]=0.f; acc4[j][1]=0.f; acc4[j][2]=0.f; acc4[j][3]=0.f; }
        #pragma unroll
        for (int kb = 0; kb < 8; kb++)
            gemm_step_r<8>(smc, ah[kb], al[kb], buf + kb * 64, 576, g, q, acc4);
        __syncthreads();
        if (nc + 2 < 8) {
            cppad<64, 32, 576>(sb + buf, gW4 + (size_t)(nc + 2) * 64 * 512, t);
            CPCOMMIT();
        }
        // epilogue 4: +b4, store fp32
        #pragma unroll
        for (int j = 0; j < 8; j++) {
            int col = nc * 64 + j * 8 + q * 2;
            float bb0 = bias[288 + col], bb1 = bias[288 + col + 1];
            float2 o0 = make_float2(acc4[j][0] + bb0, acc4[j][1] + bb1);
            float2 o1 = make_float2(acc4[j][2] + bb0, acc4[j][3] + bb1);
            *(float2*)(out + (size_t)(row0 + w * 16 + g)     * 512 + col) = o0;
            *(float2*)(out + (size_t)(row0 + w * 16 + g + 8) * 512 + col) = o1;
        }
    }
}

extern "C" void kernel_launch(void* const* d_in, const int* in_sizes, int n_in,
                              void* d_out, int out_size) {
    const float* x     = (const float*)d_in[0];
    const float* noise = (const float*)d_in[1];
    const float* hch   = (const float*)d_in[2];
    const float* W1    = (const float*)d_in[3];
    const float* b1    = (const float*)d_in[4];
    const float* W2    = (const float*)d_in[5];
    const float* b2    = (const float*)d_in[6];
    const float* W3    = (const float*)d_in[7];
    const float* b3    = (const float*)d_in[8];
    const float* W4    = (const float*)d_in[9];
    const float* b4    = (const float*)d_in[10];
    float* out = (float*)d_out;

    static int configured = 0;
    if (!configured) {
        cudaFuncSetAttribute(channel_net_kernel,
                             cudaFuncAttributeMaxDynamicSharedMemorySize, SM_TOTAL);
        configured = 1;
    }
    setup_kernel<<<136, 256>>>(W1, W2, W3, W4);
    channel_net_kernel<<<1024, 256, SM_TOTAL>>>(
        x, noise, hch, b1, b2, b3, b4, out);
}